// round 15
// baseline (speedup 1.0000x reference)
#include <cuda_runtime.h>
#include <cuda_fp16.h>
#include <math.h>

#define N_NODES 8192
#define P_META 3
#define IN_F 256
#define HIDD 64
#define N_HEADS 8
#define HD 512
#define OUT_F 64
#define NE 262144

// ---------------- scratch (static device allocations) ----------------
__device__ __half d_feat16[P_META][N_NODES * HD];   // 24 MB (sole feat copy)
__device__ __half d_zp16[P_META][N_NODES * HD];     // 24 MB (fp16 zp)
__device__ float  d_el[P_META][N_NODES * N_HEADS];
__device__ float  d_er[P_META][N_NODES * N_HEADS];
__device__ float  d_invd[P_META][N_NODES * N_HEADS];
__device__ int    d_counts[P_META][N_NODES];
__device__ int    d_cursor[P_META][N_NODES];
__device__ int    d_offsets[P_META][N_NODES + 1];
__device__ int    d_csrsrc[P_META][NE];
__device__ float  d_wsum[P_META];
__device__ float  d_v[HD];
__device__ float  d_c;

// inline beta from wsum (3-way softmax)
__device__ __forceinline__ float3 compute_beta() {
    float w0 = d_wsum[0] * (1.f / (float)N_NODES);
    float w1 = d_wsum[1] * (1.f / (float)N_NODES);
    float w2 = d_wsum[2] * (1.f / (float)N_NODES);
    float mx = fmaxf(w0, fmaxf(w1, w2));
    float e0 = __expf(w0 - mx), e1 = __expf(w1 - mx), e2 = __expf(w2 - mx);
    float inv = 1.f / (e0 + e1 + e2);
    return make_float3(e0 * inv, e1 * inv, e2 * inv);
}

// ---------------------------------------------------------------- utilities
__global__ void zero_misc_kernel() {
    int p = blockIdx.y;
    int i = blockIdx.x * blockDim.x + threadIdx.x;
    if (i < N_NODES) d_counts[p][i] = 0;
    if (p == 0 && i < P_META) d_wsum[i] = 0.f;
}

__global__ void zero_atten_kernel(float4* a) {
    int i = blockIdx.x * blockDim.x + threadIdx.x;
    a[i] = make_float4(0.f, 0.f, 0.f, 0.f);
}

// ------------------------------------------------ feat = h @ fc_p
// Packed-pair fp32 GEMM: fma.rn.f32x2 (Blackwell FFMA2) — 2 fp32 MACs/instr.
// Same numerics as fp32 FFMA; halves the fma-pipe instruction count.
__global__ void __launch_bounds__(256, 2)
gemm_feat_kernel(const float* __restrict__ A,    // [8192,256]
                 const float* __restrict__ fc) { // [P,256,512]
    const int p = blockIdx.z;
    const float* __restrict__ B = fc + (size_t)p * IN_F * HD;
    __half* __restrict__ C16 = d_feat16[p];
    __shared__ float As[8][128];
    __shared__ float Bs[8][128];
    const int bm = blockIdx.y * 128;
    const int bn = blockIdx.x * 128;
    const int t = threadIdx.x;
    const int ty = t >> 4, tx = t & 15;

    const int arow = t >> 1;
    const int acol = (t & 1) * 4;
    const int brow = t >> 5;
    const int bcol = (t & 31) * 4;

    // accp[i][j2] holds columns (2*j2, 2*j2+1) of row i as packed f32x2
    unsigned long long accp[8][4];
#pragma unroll
    for (int i = 0; i < 8; i++)
#pragma unroll
        for (int j = 0; j < 4; j++) accp[i][j] = 0ull;   // two +0.0f

    for (int k0 = 0; k0 < IN_F; k0 += 8) {
        float4 av = *(const float4*)&A[(size_t)(bm + arow) * IN_F + k0 + acol];
        float4 bv = *(const float4*)&B[(size_t)(k0 + brow) * HD + bn + bcol];
        __syncthreads();
        As[acol + 0][arow] = av.x;
        As[acol + 1][arow] = av.y;
        As[acol + 2][arow] = av.z;
        As[acol + 3][arow] = av.w;
        *(float4*)&Bs[brow][bcol] = bv;
        __syncthreads();
#pragma unroll
        for (int k = 0; k < 8; k++) {
            float a[8];
            *(float4*)&a[0] = *(const float4*)&As[k][ty * 8];
            *(float4*)&a[4] = *(const float4*)&As[k][ty * 8 + 4];
            unsigned long long ap[8];
#pragma unroll
            for (int i = 0; i < 8; i++)
                asm("mov.b64 %0, {%1, %1};" : "=l"(ap[i]) : "f"(a[i]));
            unsigned long long bp[4];
#pragma unroll
            for (int j = 0; j < 4; j++)
                bp[j] = *(const unsigned long long*)&Bs[k][tx * 8 + j * 2];
#pragma unroll
            for (int i = 0; i < 8; i++)
#pragma unroll
                for (int j = 0; j < 4; j++)
                    asm("fma.rn.f32x2 %0, %1, %2, %0;"
                        : "+l"(accp[i][j]) : "l"(ap[i]), "l"(bp[j]));
        }
    }
#pragma unroll
    for (int i = 0; i < 8; i++) {
        size_t roff = (size_t)(bm + ty * 8 + i) * HD + bn + tx * 8;
        __half2* hr = (__half2*)&C16[roff];
#pragma unroll
        for (int j = 0; j < 4; j++) {
            float lo, hi;
            asm("mov.b64 {%0, %1}, %2;" : "=f"(lo), "=f"(hi) : "l"(accp[i][j]));
            hr[j] = __floats2half2_rn(lo, hi);
        }
    }
}

// ------------------------------------------------ el/er per (node, head, p)
__global__ void eler_kernel(const float* __restrict__ al,
                            const float* __restrict__ ar) {
    int p = blockIdx.y;
    int n = blockIdx.x;
    int h = threadIdx.x >> 5;
    int lane = threadIdx.x & 31;
    float2 f = __half22float2(
        *(const __half2*)&d_feat16[p][(size_t)n * HD + h * HIDD + lane * 2]);
    float2 a = *(const float2*)&al[p * HD + h * HIDD + lane * 2];
    float2 b = *(const float2*)&ar[p * HD + h * HIDD + lane * 2];
    float sl = f.x * a.x + f.y * a.y;
    float sr = f.x * b.x + f.y * b.y;
#pragma unroll
    for (int o = 16; o; o >>= 1) {
        sl += __shfl_xor_sync(0xffffffffu, sl, o);
        sr += __shfl_xor_sync(0xffffffffu, sr, o);
    }
    if (lane == 0) {
        d_el[p][n * N_HEADS + h] = sl;
        d_er[p][n * N_HEADS + h] = sr;
    }
}

// ------------------------------------------------ CSR build by dst
__global__ void hist_kernel(const int* __restrict__ dst) {
    int p = blockIdx.y;
    int e = blockIdx.x * blockDim.x + threadIdx.x;
    if (e < NE) atomicAdd(&d_counts[p][dst[p * NE + e]], 1);
}

__global__ void scan_kernel() {
    int p = blockIdx.x;
    __shared__ int sh[1024];
    int t = threadIdx.x;
    int base = t * 8;
    int loc[8];
    int s = 0;
#pragma unroll
    for (int i = 0; i < 8; i++) { loc[i] = s; s += d_counts[p][base + i]; }
    sh[t] = s;
    __syncthreads();
    for (int ofs = 1; ofs < 1024; ofs <<= 1) {
        int v = (t >= ofs) ? sh[t - ofs] : 0;
        __syncthreads();
        sh[t] += v;
        __syncthreads();
    }
    int pre = (t == 0) ? 0 : sh[t - 1];
#pragma unroll
    for (int i = 0; i < 8; i++) {
        int o = pre + loc[i];
        d_offsets[p][base + i] = o;
        d_cursor[p][base + i] = o;
    }
    if (t == 1023) d_offsets[p][N_NODES] = sh[1023];
}

__global__ void csr_scatter_kernel(const int* __restrict__ src,
                                   const int* __restrict__ dst) {
    int p = blockIdx.y;
    int e = blockIdx.x * blockDim.x + threadIdx.x;
    if (e < NE) {
        int pos = atomicAdd(&d_cursor[p][dst[p * NE + e]], 1);
        d_csrsrc[p][pos] = src[p * NE + e];
    }
}

// ------------------------------------------------ aggregation (R14 best)
__global__ void gat_aggregate_kernel(const float* __restrict__ bias) {
    int p = blockIdx.y;
    int dn = blockIdx.x;
    int h = threadIdx.x >> 5;
    int lane = threadIdx.x & 31;
    int s0 = d_offsets[p][dn], s1 = d_offsets[p][dn + 1];
    float erv = d_er[p][dn * N_HEADS + h];
    const float* __restrict__ el = d_el[p];
    const int* __restrict__ csrc = d_csrsrc[p];
    const __half* fb = &d_feat16[p][h * HIDD + lane * 2];

    float ssum = 0.f, accx = 0.f, accy = 0.f;
    int i = s0;
    for (; i + 8 <= s1; i += 8) {
        int sx[8];
#pragma unroll
        for (int u = 0; u < 8; u++) sx[u] = csrc[i + u];
        float ex[8];
#pragma unroll
        for (int u = 0; u < 8; u++) ex[u] = el[sx[u] * N_HEADS + h];
        float2 fx[8];
#pragma unroll
        for (int u = 0; u < 8; u++)
            fx[u] = __half22float2(*(const __half2*)(fb + (size_t)sx[u] * HD));
#pragma unroll
        for (int u = 0; u < 8; u++) {
            float v = ex[u] + erv;
            v = v > 0.f ? v : 0.2f * v;
            float a = __expf(v);
            ssum += a;
            accx += a * fx[u].x;
            accy += a * fx[u].y;
        }
    }
    for (; i < s1; i++) {
        int s = csrc[i];
        float ev = el[s * N_HEADS + h] + erv;
        ev = ev > 0.f ? ev : 0.2f * ev;
        float a = __expf(ev);
        float2 f = __half22float2(*(const __half2*)(fb + (size_t)s * HD));
        ssum += a;
        accx += a * f.x;
        accy += a * f.y;
    }
    float inv = ssum > 0.f ? 1.f / ssum : 0.f;
    if (lane == 0) d_invd[p][dn * N_HEADS + h] = inv;

    float bx = bias[p * HD + h * HIDD + lane * 2];
    float by = bias[p * HD + h * HIDD + lane * 2 + 1];
    float ox = accx * inv + bx, oy = accy * inv + by;
    ox = ox > 0.f ? ox : (__expf(ox) - 1.f);
    oy = oy > 0.f ? oy : (__expf(oy) - 1.f);
    *(__half2*)&d_zp16[p][(size_t)dn * HD + h * HIDD + lane * 2] =
        __floats2half2_rn(ox, oy);
}

// ------------------------------------------------ semantic attention
__global__ void sem_v_kernel(const float* __restrict__ w1,
                             const float* __restrict__ w2,
                             const float* __restrict__ b1) {
    int k = threadIdx.x + blockIdx.x * blockDim.x;
    float s = 0.f;
    for (int j = 0; j < 128; j++) s += w1[k * 128 + j] * w2[j];
    d_v[k] = s;
    if (k == 0) {
        float c = 0.f;
        for (int j = 0; j < 128; j++) c += b1[j] * w2[j];
        d_c = c;
    }
}

__global__ void sem_w_kernel() {
    int gw = (blockIdx.x * blockDim.x + threadIdx.x) >> 5;
    int lane = threadIdx.x & 31;
    int n = gw / P_META;
    int p = gw - n * P_META;
    if (n >= N_NODES) return;
    const __half* z = &d_zp16[p][(size_t)n * HD];
    float s = 0.f;
#pragma unroll
    for (int k2 = lane; k2 < HD / 2; k2 += 32) {
        float2 f = __half22float2(((const __half2*)z)[k2]);
        s += f.x * d_v[k2 * 2] + f.y * d_v[k2 * 2 + 1];
    }
#pragma unroll
    for (int o = 16; o; o >>= 1) s += __shfl_xor_sync(0xffffffffu, s, o);
    if (lane == 0) {
        float w = s + d_c;
        w = w > 0.f ? w : 0.01f * w;
        atomicAdd(&d_wsum[p], w);
    }
}

// ------------------------------------------------ out = (Σp beta_p zp) @ pred_w + pred_b
__global__ void out_kernel(const float* __restrict__ pw,
                           const float* __restrict__ pb,
                           float* __restrict__ out) {
    __shared__ float zs[HD];
    int n = blockIdx.x;
    int t = threadIdx.x;   // 64
    float3 bt = compute_beta();
    for (int k2 = t; k2 < HD / 2; k2 += 64) {
        size_t off2 = (size_t)n * (HD / 2) + k2;
        float2 a = __half22float2(((const __half2*)d_zp16[0])[off2]);
        float2 b = __half22float2(((const __half2*)d_zp16[1])[off2]);
        float2 c = __half22float2(((const __half2*)d_zp16[2])[off2]);
        zs[k2 * 2]     = bt.x * a.x + bt.y * b.x + bt.z * c.x;
        zs[k2 * 2 + 1] = bt.x * a.y + bt.y * b.y + bt.z * c.y;
    }
    __syncthreads();
    float acc = pb[t];
#pragma unroll 8
    for (int k = 0; k < HD; k++) acc += zs[k] * pw[k * OUT_F + t];
    out[(size_t)n * OUT_F + t] = acc;
}

// ------------------------------------------------ atten scatter (fused alpha+beta)
__global__ void atten_scatter_kernel(const int* __restrict__ src,
                                     const int* __restrict__ dst,
                                     float* __restrict__ atten) {
    int p = blockIdx.y;
    int e = blockIdx.x * blockDim.x + threadIdx.x;
    if (e >= NE) return;
    float3 bt = compute_beta();
    float betap = (p == 0) ? bt.x : (p == 1) ? bt.y : bt.z;
    int s = src[p * NE + e];
    int d = dst[p * NE + e];
    const float* elrow = &d_el[p][s * N_HEADS];
    const float* errow = &d_er[p][d * N_HEADS];
    const float* invrow = &d_invd[p][d * N_HEADS];
    float a = 0.f;
#pragma unroll
    for (int h = 0; h < N_HEADS; h++) {
        float ev = elrow[h] + errow[h];
        ev = ev > 0.f ? ev : 0.2f * ev;
        a += __expf(ev) * invrow[h];
    }
    float v = a * 0.125f * betap;
    atomicAdd(&atten[(size_t)s * N_NODES + d], v);
}

// ---------------------------------------------------------------- launcher
extern "C" void kernel_launch(void* const* d_in, const int* in_sizes, int n_in,
                              void* d_out, int out_size) {
    const float* h    = (const float*)d_in[0];
    const int*   esrc = (const int*)d_in[1];
    const int*   edst = (const int*)d_in[2];
    const float* fc   = (const float*)d_in[3];
    const float* al   = (const float*)d_in[4];
    const float* ar   = (const float*)d_in[5];
    const float* bias = (const float*)d_in[6];
    const float* w1   = (const float*)d_in[7];
    const float* b1   = (const float*)d_in[8];
    const float* w2   = (const float*)d_in[9];
    const float* pw   = (const float*)d_in[10];
    const float* pb   = (const float*)d_in[11];

    const long long SZ_OUT   = (long long)N_NODES * OUT_F;
    const long long SZ_ATTEN = (long long)N_NODES * N_NODES;
    long long osz = (long long)out_size;

    float* out_ptr = nullptr;
    float* atten_ptr = nullptr;
    if (osz >= SZ_OUT + SZ_ATTEN) {
        out_ptr = (float*)d_out;
        atten_ptr = out_ptr + SZ_OUT;
    } else if (osz == SZ_OUT) {
        out_ptr = (float*)d_out;
    } else if (osz == SZ_ATTEN) {
        atten_ptr = (float*)d_out;
    } else {
        out_ptr = (float*)d_out;
    }

    static cudaStream_t sA = (cudaStream_t)0, sB = (cudaStream_t)0;
    static cudaEvent_t evFork = nullptr, evA = nullptr, evC = nullptr, evB = nullptr;
    static int streams_ok = -1;
    if (streams_ok < 0) {
        cudaStream_t t1, t2;
        cudaEvent_t e0, e1, e2, e3;
        if (cudaStreamCreateWithFlags(&t1, cudaStreamNonBlocking) == cudaSuccess &&
            cudaStreamCreateWithFlags(&t2, cudaStreamNonBlocking) == cudaSuccess &&
            cudaEventCreateWithFlags(&e0, cudaEventDisableTiming) == cudaSuccess &&
            cudaEventCreateWithFlags(&e1, cudaEventDisableTiming) == cudaSuccess &&
            cudaEventCreateWithFlags(&e2, cudaEventDisableTiming) == cudaSuccess &&
            cudaEventCreateWithFlags(&e3, cudaEventDisableTiming) == cudaSuccess) {
            sA = t1; sB = t2; evFork = e0; evA = e1; evC = e2; evB = e3;
            streams_ok = 1;
        } else {
            streams_ok = 0;
        }
    }
    cudaStream_t strA = streams_ok ? sA : (cudaStream_t)0;
    cudaStream_t strB = streams_ok ? sB : (cudaStream_t)0;

    if (streams_ok) {
        cudaEventRecord(evFork, (cudaStream_t)0);
        cudaStreamWaitEvent(strA, evFork, 0);
        cudaStreamWaitEvent(strB, evFork, 0);
    }

    // stream A: CSR build chain (joins before aggregate)
    zero_misc_kernel<<<dim3(N_NODES / 256, P_META), 256, 0, strA>>>();
    hist_kernel<<<dim3(NE / 256, P_META), 256, 0, strA>>>(edst);
    scan_kernel<<<P_META, 1024, 0, strA>>>();
    csr_scatter_kernel<<<dim3(NE / 256, P_META), 256, 0, strA>>>(esrc, edst);

    // stream B: atten zero-fill
    if (atten_ptr)
        zero_atten_kernel<<<(N_NODES * (N_NODES / 4)) / 256, 256, 0, strB>>>(
            (float4*)atten_ptr);

    // main: GEMM (f32x2, fp16 out) + el/er
    gemm_feat_kernel<<<dim3(HD / 128, N_NODES / 128, P_META), 256>>>(h, fc);
    eler_kernel<<<dim3(N_NODES, P_META), 256>>>(al, ar);

    if (streams_ok) {
        cudaEventRecord(evA, strA);
        cudaStreamWaitEvent((cudaStream_t)0, evA, 0);
    }

    gat_aggregate_kernel<<<dim3(N_NODES, P_META), 256>>>(bias);

    sem_v_kernel<<<2, 256>>>(w1, w2, b1);
    sem_w_kernel<<<(N_NODES * P_META * 32) / 256, 256>>>();

    if (atten_ptr && streams_ok) {
        cudaEventRecord(evC, (cudaStream_t)0);   // after sem_w (wsum ready)
        cudaStreamWaitEvent(strB, evC, 0);
        atten_scatter_kernel<<<dim3(NE / 256, P_META), 256, 0, strB>>>(
            esrc, edst, atten_ptr);
        cudaEventRecord(evB, strB);
    }

    if (out_ptr)
        out_kernel<<<N_NODES, 64>>>(pw, pb, out_ptr);

    if (atten_ptr) {
        if (streams_ok) {
            cudaStreamWaitEvent((cudaStream_t)0, evB, 0);
        } else {
            atten_scatter_kernel<<<dim3(NE / 256, P_META), 256>>>(esrc, edst,
                                                                  atten_ptr);
        }
    }
}

// round 16
// speedup vs baseline: 1.0336x; 1.0336x over previous
#include <cuda_runtime.h>
#include <cuda_fp16.h>
#include <math.h>

#define N_NODES 8192
#define P_META 3
#define IN_F 256
#define HIDD 64
#define N_HEADS 8
#define HD 512
#define OUT_F 64
#define NE 262144

// ---------------- scratch (static device allocations) ----------------
__device__ __half d_feat16[P_META][N_NODES * HD];   // 24 MB
__device__ __half d_zp16[P_META][N_NODES * HD];     // 24 MB
__device__ float  d_el[P_META][N_NODES * N_HEADS];
__device__ float  d_er[P_META][N_NODES * N_HEADS];
__device__ float  d_invd[P_META][N_NODES * N_HEADS];
__device__ int    d_counts[P_META][N_NODES];
__device__ int    d_cursor[P_META][N_NODES];
__device__ int    d_offsets[P_META][N_NODES + 1];
__device__ int    d_csrsrc[P_META][NE];
__device__ float  d_wsum[P_META];
__device__ float  d_v[HD];
__device__ float  d_c;

__device__ __forceinline__ float3 compute_beta() {
    float w0 = d_wsum[0] * (1.f / (float)N_NODES);
    float w1 = d_wsum[1] * (1.f / (float)N_NODES);
    float w2 = d_wsum[2] * (1.f / (float)N_NODES);
    float mx = fmaxf(w0, fmaxf(w1, w2));
    float e0 = __expf(w0 - mx), e1 = __expf(w1 - mx), e2 = __expf(w2 - mx);
    float inv = 1.f / (e0 + e1 + e2);
    return make_float3(e0 * inv, e1 * inv, e2 * inv);
}

// ---------------------------------------------------------------- utilities
__global__ void zero_misc_kernel() {
    int p = blockIdx.y;
    int i = blockIdx.x * blockDim.x + threadIdx.x;
    if (i < N_NODES) d_counts[p][i] = 0;
    if (p == 0 && i < P_META) d_wsum[i] = 0.f;
}

__global__ void zero_atten_kernel(float4* a) {
    int i = blockIdx.x * blockDim.x + threadIdx.x;
    a[i] = make_float4(0.f, 0.f, 0.f, 0.f);
}

// ------------------------------------------------ feat = h @ fc_p (fp32 FFMA)
// Per-p launch (grid 4x64) so aggregate(p) can overlap gemm(p+1).
__global__ void __launch_bounds__(256, 2)
gemm_feat_kernel(const float* __restrict__ A,    // [8192,256]
                 const float* __restrict__ fc,   // [P,256,512]
                 int p) {
    const float* __restrict__ B = fc + (size_t)p * IN_F * HD;
    __half* __restrict__ C16 = d_feat16[p];
    __shared__ float As[8][128];
    __shared__ float Bs[8][128];
    const int bm = blockIdx.y * 128;
    const int bn = blockIdx.x * 128;
    const int t = threadIdx.x;
    const int ty = t >> 4, tx = t & 15;

    const int arow = t >> 1;
    const int acol = (t & 1) * 4;
    const int brow = t >> 5;
    const int bcol = (t & 31) * 4;

    float acc[8][8];
#pragma unroll
    for (int i = 0; i < 8; i++)
#pragma unroll
        for (int j = 0; j < 8; j++) acc[i][j] = 0.f;

    for (int k0 = 0; k0 < IN_F; k0 += 8) {
        float4 av = *(const float4*)&A[(size_t)(bm + arow) * IN_F + k0 + acol];
        float4 bv = *(const float4*)&B[(size_t)(k0 + brow) * HD + bn + bcol];
        __syncthreads();
        As[acol + 0][arow] = av.x;
        As[acol + 1][arow] = av.y;
        As[acol + 2][arow] = av.z;
        As[acol + 3][arow] = av.w;
        *(float4*)&Bs[brow][bcol] = bv;
        __syncthreads();
#pragma unroll
        for (int k = 0; k < 8; k++) {
            float a[8], b[8];
            *(float4*)&a[0] = *(const float4*)&As[k][ty * 8];
            *(float4*)&a[4] = *(const float4*)&As[k][ty * 8 + 4];
            *(float4*)&b[0] = *(const float4*)&Bs[k][tx * 8];
            *(float4*)&b[4] = *(const float4*)&Bs[k][tx * 8 + 4];
#pragma unroll
            for (int i = 0; i < 8; i++)
#pragma unroll
                for (int j = 0; j < 8; j++) acc[i][j] += a[i] * b[j];
        }
    }
#pragma unroll
    for (int i = 0; i < 8; i++) {
        size_t roff = (size_t)(bm + ty * 8 + i) * HD + bn + tx * 8;
        __half2* hr = (__half2*)&C16[roff];
        hr[0] = __floats2half2_rn(acc[i][0], acc[i][1]);
        hr[1] = __floats2half2_rn(acc[i][2], acc[i][3]);
        hr[2] = __floats2half2_rn(acc[i][4], acc[i][5]);
        hr[3] = __floats2half2_rn(acc[i][6], acc[i][7]);
    }
}

// ------------------------------------------------ el/er per (node, head) for one p
__global__ void eler_kernel(const float* __restrict__ al,
                            const float* __restrict__ ar, int p) {
    int n = blockIdx.x;
    int h = threadIdx.x >> 5;
    int lane = threadIdx.x & 31;
    float2 f = __half22float2(
        *(const __half2*)&d_feat16[p][(size_t)n * HD + h * HIDD + lane * 2]);
    float2 a = *(const float2*)&al[p * HD + h * HIDD + lane * 2];
    float2 b = *(const float2*)&ar[p * HD + h * HIDD + lane * 2];
    float sl = f.x * a.x + f.y * a.y;
    float sr = f.x * b.x + f.y * b.y;
#pragma unroll
    for (int o = 16; o; o >>= 1) {
        sl += __shfl_xor_sync(0xffffffffu, sl, o);
        sr += __shfl_xor_sync(0xffffffffu, sr, o);
    }
    if (lane == 0) {
        d_el[p][n * N_HEADS + h] = sl;
        d_er[p][n * N_HEADS + h] = sr;
    }
}

// ------------------------------------------------ CSR build by dst (batched)
__global__ void hist_kernel(const int* __restrict__ dst) {
    int p = blockIdx.y;
    int e = blockIdx.x * blockDim.x + threadIdx.x;
    if (e < NE) atomicAdd(&d_counts[p][dst[p * NE + e]], 1);
}

__global__ void scan_kernel() {
    int p = blockIdx.x;
    __shared__ int sh[1024];
    int t = threadIdx.x;
    int base = t * 8;
    int loc[8];
    int s = 0;
#pragma unroll
    for (int i = 0; i < 8; i++) { loc[i] = s; s += d_counts[p][base + i]; }
    sh[t] = s;
    __syncthreads();
    for (int ofs = 1; ofs < 1024; ofs <<= 1) {
        int v = (t >= ofs) ? sh[t - ofs] : 0;
        __syncthreads();
        sh[t] += v;
        __syncthreads();
    }
    int pre = (t == 0) ? 0 : sh[t - 1];
#pragma unroll
    for (int i = 0; i < 8; i++) {
        int o = pre + loc[i];
        d_offsets[p][base + i] = o;
        d_cursor[p][base + i] = o;
    }
    if (t == 1023) d_offsets[p][N_NODES] = sh[1023];
}

__global__ void csr_scatter_kernel(const int* __restrict__ src,
                                   const int* __restrict__ dst) {
    int p = blockIdx.y;
    int e = blockIdx.x * blockDim.x + threadIdx.x;
    if (e < NE) {
        int pos = atomicAdd(&d_cursor[p][dst[p * NE + e]], 1);
        d_csrsrc[p][pos] = src[p * NE + e];
    }
}

// ------------------------------------------------ aggregation for one p
__global__ void gat_aggregate_kernel(const float* __restrict__ bias, int p) {
    int dn = blockIdx.x;
    int h = threadIdx.x >> 5;
    int lane = threadIdx.x & 31;
    int s0 = d_offsets[p][dn], s1 = d_offsets[p][dn + 1];
    float erv = d_er[p][dn * N_HEADS + h];
    const float* __restrict__ el = d_el[p];
    const int* __restrict__ csrc = d_csrsrc[p];
    const __half* fb = &d_feat16[p][h * HIDD + lane * 2];

    float ssum = 0.f, accx = 0.f, accy = 0.f;
    int i = s0;
    for (; i + 8 <= s1; i += 8) {
        int sx[8];
#pragma unroll
        for (int u = 0; u < 8; u++) sx[u] = csrc[i + u];
        float ex[8];
#pragma unroll
        for (int u = 0; u < 8; u++) ex[u] = el[sx[u] * N_HEADS + h];
        float2 fx[8];
#pragma unroll
        for (int u = 0; u < 8; u++)
            fx[u] = __half22float2(*(const __half2*)(fb + (size_t)sx[u] * HD));
#pragma unroll
        for (int u = 0; u < 8; u++) {
            float v = ex[u] + erv;
            v = v > 0.f ? v : 0.2f * v;
            float a = __expf(v);
            ssum += a;
            accx += a * fx[u].x;
            accy += a * fx[u].y;
        }
    }
    for (; i < s1; i++) {
        int s = csrc[i];
        float ev = el[s * N_HEADS + h] + erv;
        ev = ev > 0.f ? ev : 0.2f * ev;
        float a = __expf(ev);
        float2 f = __half22float2(*(const __half2*)(fb + (size_t)s * HD));
        ssum += a;
        accx += a * f.x;
        accy += a * f.y;
    }
    float inv = ssum > 0.f ? 1.f / ssum : 0.f;
    if (lane == 0) d_invd[p][dn * N_HEADS + h] = inv;

    float bx = bias[p * HD + h * HIDD + lane * 2];
    float by = bias[p * HD + h * HIDD + lane * 2 + 1];
    float ox = accx * inv + bx, oy = accy * inv + by;
    ox = ox > 0.f ? ox : (__expf(ox) - 1.f);
    oy = oy > 0.f ? oy : (__expf(oy) - 1.f);
    *(__half2*)&d_zp16[p][(size_t)dn * HD + h * HIDD + lane * 2] =
        __floats2half2_rn(ox, oy);
}

// ------------------------------------------------ semantic attention
__global__ void sem_v_kernel(const float* __restrict__ w1,
                             const float* __restrict__ w2,
                             const float* __restrict__ b1) {
    int k = threadIdx.x + blockIdx.x * blockDim.x;
    float s = 0.f;
    for (int j = 0; j < 128; j++) s += w1[k * 128 + j] * w2[j];
    d_v[k] = s;
    if (k == 0) {
        float c = 0.f;
        for (int j = 0; j < 128; j++) c += b1[j] * w2[j];
        d_c = c;
    }
}

__global__ void sem_w_kernel() {
    int gw = (blockIdx.x * blockDim.x + threadIdx.x) >> 5;
    int lane = threadIdx.x & 31;
    int n = gw / P_META;
    int p = gw - n * P_META;
    if (n >= N_NODES) return;
    const __half* z = &d_zp16[p][(size_t)n * HD];
    float s = 0.f;
#pragma unroll
    for (int k2 = lane; k2 < HD / 2; k2 += 32) {
        float2 f = __half22float2(((const __half2*)z)[k2]);
        s += f.x * d_v[k2 * 2] + f.y * d_v[k2 * 2 + 1];
    }
#pragma unroll
    for (int o = 16; o; o >>= 1) s += __shfl_xor_sync(0xffffffffu, s, o);
    if (lane == 0) {
        float w = s + d_c;
        w = w > 0.f ? w : 0.01f * w;
        atomicAdd(&d_wsum[p], w);
    }
}

// ------------------------------------------------ out = (Σp beta_p zp) @ pred_w + pred_b
__global__ void out_kernel(const float* __restrict__ pw,
                           const float* __restrict__ pb,
                           float* __restrict__ out) {
    __shared__ float zs[HD];
    int n = blockIdx.x;
    int t = threadIdx.x;   // 64
    float3 bt = compute_beta();
    for (int k2 = t; k2 < HD / 2; k2 += 64) {
        size_t off2 = (size_t)n * (HD / 2) + k2;
        float2 a = __half22float2(((const __half2*)d_zp16[0])[off2]);
        float2 b = __half22float2(((const __half2*)d_zp16[1])[off2]);
        float2 c = __half22float2(((const __half2*)d_zp16[2])[off2]);
        zs[k2 * 2]     = bt.x * a.x + bt.y * b.x + bt.z * c.x;
        zs[k2 * 2 + 1] = bt.x * a.y + bt.y * b.y + bt.z * c.y;
    }
    __syncthreads();
    float acc = pb[t];
#pragma unroll 8
    for (int k = 0; k < HD; k++) acc += zs[k] * pw[k * OUT_F + t];
    out[(size_t)n * OUT_F + t] = acc;
}

// ------------------------------------------------ atten scatter (fused alpha+beta)
__global__ void atten_scatter_kernel(const int* __restrict__ src,
                                     const int* __restrict__ dst,
                                     float* __restrict__ atten) {
    int p = blockIdx.y;
    int e = blockIdx.x * blockDim.x + threadIdx.x;
    if (e >= NE) return;
    float3 bt = compute_beta();
    float betap = (p == 0) ? bt.x : (p == 1) ? bt.y : bt.z;
    int s = src[p * NE + e];
    int d = dst[p * NE + e];
    const float* elrow = &d_el[p][s * N_HEADS];
    const float* errow = &d_er[p][d * N_HEADS];
    const float* invrow = &d_invd[p][d * N_HEADS];
    float a = 0.f;
#pragma unroll
    for (int h = 0; h < N_HEADS; h++) {
        float ev = elrow[h] + errow[h];
        ev = ev > 0.f ? ev : 0.2f * ev;
        a += __expf(ev) * invrow[h];
    }
    float v = a * 0.125f * betap;
    atomicAdd(&atten[(size_t)s * N_NODES + d], v);
}

// ---------------------------------------------------------------- launcher
extern "C" void kernel_launch(void* const* d_in, const int* in_sizes, int n_in,
                              void* d_out, int out_size) {
    const float* h    = (const float*)d_in[0];
    const int*   esrc = (const int*)d_in[1];
    const int*   edst = (const int*)d_in[2];
    const float* fc   = (const float*)d_in[3];
    const float* al   = (const float*)d_in[4];
    const float* ar   = (const float*)d_in[5];
    const float* bias = (const float*)d_in[6];
    const float* w1   = (const float*)d_in[7];
    const float* b1   = (const float*)d_in[8];
    const float* w2   = (const float*)d_in[9];
    const float* pw   = (const float*)d_in[10];
    const float* pb   = (const float*)d_in[11];

    const long long SZ_OUT   = (long long)N_NODES * OUT_F;
    const long long SZ_ATTEN = (long long)N_NODES * N_NODES;
    long long osz = (long long)out_size;

    float* out_ptr = nullptr;
    float* atten_ptr = nullptr;
    if (osz >= SZ_OUT + SZ_ATTEN) {
        out_ptr = (float*)d_out;
        atten_ptr = out_ptr + SZ_OUT;
    } else if (osz == SZ_OUT) {
        out_ptr = (float*)d_out;
    } else if (osz == SZ_ATTEN) {
        atten_ptr = (float*)d_out;
    } else {
        out_ptr = (float*)d_out;
    }

    // streams: A = CSR, B = zero_atten + scatter, C = aggregate/sem/out
    static cudaStream_t sA = 0, sB = 0, sC = 0;
    static cudaEvent_t evFork = nullptr, evCSR = nullptr, evW = nullptr,
                       evB = nullptr, evC = nullptr;
    static cudaEvent_t evG[P_META] = {nullptr, nullptr, nullptr};
    static int streams_ok = -1;
    if (streams_ok < 0) {
        cudaStream_t t1, t2, t3;
        cudaEvent_t e0, e1, e2, e3, e4, g0, g1, g2;
        bool ok =
            cudaStreamCreateWithFlags(&t1, cudaStreamNonBlocking) == cudaSuccess &&
            cudaStreamCreateWithFlags(&t2, cudaStreamNonBlocking) == cudaSuccess &&
            cudaStreamCreateWithFlags(&t3, cudaStreamNonBlocking) == cudaSuccess &&
            cudaEventCreateWithFlags(&e0, cudaEventDisableTiming) == cudaSuccess &&
            cudaEventCreateWithFlags(&e1, cudaEventDisableTiming) == cudaSuccess &&
            cudaEventCreateWithFlags(&e2, cudaEventDisableTiming) == cudaSuccess &&
            cudaEventCreateWithFlags(&e3, cudaEventDisableTiming) == cudaSuccess &&
            cudaEventCreateWithFlags(&e4, cudaEventDisableTiming) == cudaSuccess &&
            cudaEventCreateWithFlags(&g0, cudaEventDisableTiming) == cudaSuccess &&
            cudaEventCreateWithFlags(&g1, cudaEventDisableTiming) == cudaSuccess &&
            cudaEventCreateWithFlags(&g2, cudaEventDisableTiming) == cudaSuccess;
        if (ok) {
            sA = t1; sB = t2; sC = t3;
            evFork = e0; evCSR = e1; evW = e2; evB = e3; evC = e4;
            evG[0] = g0; evG[1] = g1; evG[2] = g2;
            streams_ok = 1;
        } else {
            streams_ok = 0;
        }
    }

    if (!streams_ok) {
        // sequential fallback
        zero_misc_kernel<<<dim3(N_NODES / 256, P_META), 256>>>();
        if (atten_ptr)
            zero_atten_kernel<<<(N_NODES * (N_NODES / 4)) / 256, 256>>>(
                (float4*)atten_ptr);
        hist_kernel<<<dim3(NE / 256, P_META), 256>>>(edst);
        scan_kernel<<<P_META, 1024>>>();
        csr_scatter_kernel<<<dim3(NE / 256, P_META), 256>>>(esrc, edst);
        for (int p = 0; p < P_META; p++) {
            gemm_feat_kernel<<<dim3(HD / 128, N_NODES / 128), 256>>>(h, fc, p);
            eler_kernel<<<N_NODES, 256>>>(al, ar, p);
            gat_aggregate_kernel<<<N_NODES, 256>>>(bias, p);
        }
        sem_v_kernel<<<2, 256>>>(w1, w2, b1);
        sem_w_kernel<<<(N_NODES * P_META * 32) / 256, 256>>>();
        if (out_ptr) out_kernel<<<N_NODES, 64>>>(pw, pb, out_ptr);
        if (atten_ptr)
            atten_scatter_kernel<<<dim3(NE / 256, P_META), 256>>>(esrc, edst,
                                                                  atten_ptr);
        return;
    }

    cudaEventRecord(evFork, (cudaStream_t)0);
    cudaStreamWaitEvent(sA, evFork, 0);
    cudaStreamWaitEvent(sB, evFork, 0);
    cudaStreamWaitEvent(sC, evFork, 0);

    // stream A: CSR build chain
    zero_misc_kernel<<<dim3(N_NODES / 256, P_META), 256, 0, sA>>>();
    hist_kernel<<<dim3(NE / 256, P_META), 256, 0, sA>>>(edst);
    scan_kernel<<<P_META, 1024, 0, sA>>>();
    csr_scatter_kernel<<<dim3(NE / 256, P_META), 256, 0, sA>>>(esrc, edst);
    cudaEventRecord(evCSR, sA);

    // stream B: atten zero-fill + sem_v (independent prep)
    if (atten_ptr)
        zero_atten_kernel<<<(N_NODES * (N_NODES / 4)) / 256, 256, 0, sB>>>(
            (float4*)atten_ptr);
    sem_v_kernel<<<2, 256, 0, sB>>>(w1, w2, b1);

    // main: per-p GEMM + eler, signal evG[p]
    for (int p = 0; p < P_META; p++) {
        gemm_feat_kernel<<<dim3(HD / 128, N_NODES / 128), 256>>>(h, fc, p);
        eler_kernel<<<N_NODES, 256>>>(al, ar, p);
        cudaEventRecord(evG[p], (cudaStream_t)0);
    }

    // stream C: aggregate(p) pipelined against gemm(p+1)
    cudaStreamWaitEvent(sC, evCSR, 0);
    for (int p = 0; p < P_META; p++) {
        cudaStreamWaitEvent(sC, evG[p], 0);
        gat_aggregate_kernel<<<N_NODES, 256, 0, sC>>>(bias, p);
    }
    sem_w_kernel<<<(N_NODES * P_META * 32) / 256, 256, 0, sC>>>();
    cudaEventRecord(evW, sC);

    // out on stream C; atten_scatter on stream B (after wsum + zero_atten)
    if (out_ptr)
        out_kernel<<<N_NODES, 64, 0, sC>>>(pw, pb, out_ptr);
    cudaEventRecord(evC, sC);

    if (atten_ptr) {
        cudaStreamWaitEvent(sB, evW, 0);
        atten_scatter_kernel<<<dim3(NE / 256, P_META), 256, 0, sB>>>(
            esrc, edst, atten_ptr);
    }
    cudaEventRecord(evB, sB);

    // join everything back to main
    cudaStreamWaitEvent((cudaStream_t)0, evC, 0);
    cudaStreamWaitEvent((cudaStream_t)0, evB, 0);
}

// round 17
// speedup vs baseline: 1.0372x; 1.0035x over previous
#include <cuda_runtime.h>
#include <cuda_fp16.h>
#include <math.h>

#define N_NODES 8192
#define P_META 3
#define IN_F 256
#define HIDD 64
#define N_HEADS 8
#define HD 512
#define OUT_F 64
#define NE 262144

// ---------------- scratch (static device allocations) ----------------
__device__ __half d_feat16[P_META][N_NODES * HD];   // 24 MB
__device__ __half d_zp16[P_META][N_NODES * HD];     // 24 MB
__device__ float  d_el[P_META][N_NODES * N_HEADS];
__device__ float  d_er[P_META][N_NODES * N_HEADS];
__device__ float  d_invd[P_META][N_NODES * N_HEADS];
__device__ int    d_counts[P_META][N_NODES];
__device__ int    d_cursor[P_META][N_NODES];
__device__ int    d_offsets[P_META][N_NODES + 1];
__device__ int    d_csrsrc[P_META][NE];
__device__ float  d_wsum[P_META];
__device__ float  d_v[HD];
__device__ float  d_c;

__device__ __forceinline__ float3 compute_beta() {
    float w0 = d_wsum[0] * (1.f / (float)N_NODES);
    float w1 = d_wsum[1] * (1.f / (float)N_NODES);
    float w2 = d_wsum[2] * (1.f / (float)N_NODES);
    float mx = fmaxf(w0, fmaxf(w1, w2));
    float e0 = __expf(w0 - mx), e1 = __expf(w1 - mx), e2 = __expf(w2 - mx);
    float inv = 1.f / (e0 + e1 + e2);
    return make_float3(e0 * inv, e1 * inv, e2 * inv);
}

// ---------------------------------------------------------------- utilities
__global__ void zero_misc_kernel() {
    int p = blockIdx.y;
    int i = blockIdx.x * blockDim.x + threadIdx.x;
    if (i < N_NODES) d_counts[p][i] = 0;
    if (p == 0 && i < P_META) d_wsum[i] = 0.f;
}

__global__ void zero_atten_kernel(float4* a) {
    int i = blockIdx.x * blockDim.x + threadIdx.x;
    a[i] = make_float4(0.f, 0.f, 0.f, 0.f);
}

// ------------------------------------------------ feat = h @ fc_p (fp32 FFMA)
__global__ void __launch_bounds__(256, 2)
gemm_feat_kernel(const float* __restrict__ A,    // [8192,256]
                 const float* __restrict__ fc,   // [P,256,512]
                 int p) {
    const float* __restrict__ B = fc + (size_t)p * IN_F * HD;
    __half* __restrict__ C16 = d_feat16[p];
    __shared__ float As[8][128];
    __shared__ float Bs[8][128];
    const int bm = blockIdx.y * 128;
    const int bn = blockIdx.x * 128;
    const int t = threadIdx.x;
    const int ty = t >> 4, tx = t & 15;

    const int arow = t >> 1;
    const int acol = (t & 1) * 4;
    const int brow = t >> 5;
    const int bcol = (t & 31) * 4;

    float acc[8][8];
#pragma unroll
    for (int i = 0; i < 8; i++)
#pragma unroll
        for (int j = 0; j < 8; j++) acc[i][j] = 0.f;

    for (int k0 = 0; k0 < IN_F; k0 += 8) {
        float4 av = *(const float4*)&A[(size_t)(bm + arow) * IN_F + k0 + acol];
        float4 bv = *(const float4*)&B[(size_t)(k0 + brow) * HD + bn + bcol];
        __syncthreads();
        As[acol + 0][arow] = av.x;
        As[acol + 1][arow] = av.y;
        As[acol + 2][arow] = av.z;
        As[acol + 3][arow] = av.w;
        *(float4*)&Bs[brow][bcol] = bv;
        __syncthreads();
#pragma unroll
        for (int k = 0; k < 8; k++) {
            float a[8], b[8];
            *(float4*)&a[0] = *(const float4*)&As[k][ty * 8];
            *(float4*)&a[4] = *(const float4*)&As[k][ty * 8 + 4];
            *(float4*)&b[0] = *(const float4*)&Bs[k][tx * 8];
            *(float4*)&b[4] = *(const float4*)&Bs[k][tx * 8 + 4];
#pragma unroll
            for (int i = 0; i < 8; i++)
#pragma unroll
                for (int j = 0; j < 8; j++) acc[i][j] += a[i] * b[j];
        }
    }
#pragma unroll
    for (int i = 0; i < 8; i++) {
        size_t roff = (size_t)(bm + ty * 8 + i) * HD + bn + tx * 8;
        __half2* hr = (__half2*)&C16[roff];
        hr[0] = __floats2half2_rn(acc[i][0], acc[i][1]);
        hr[1] = __floats2half2_rn(acc[i][2], acc[i][3]);
        hr[2] = __floats2half2_rn(acc[i][4], acc[i][5]);
        hr[3] = __floats2half2_rn(acc[i][6], acc[i][7]);
    }
}

// ------------------------------------------------ el/er per (node, head) for one p
__global__ void eler_kernel(const float* __restrict__ al,
                            const float* __restrict__ ar, int p) {
    int n = blockIdx.x;
    int h = threadIdx.x >> 5;
    int lane = threadIdx.x & 31;
    float2 f = __half22float2(
        *(const __half2*)&d_feat16[p][(size_t)n * HD + h * HIDD + lane * 2]);
    float2 a = *(const float2*)&al[p * HD + h * HIDD + lane * 2];
    float2 b = *(const float2*)&ar[p * HD + h * HIDD + lane * 2];
    float sl = f.x * a.x + f.y * a.y;
    float sr = f.x * b.x + f.y * b.y;
#pragma unroll
    for (int o = 16; o; o >>= 1) {
        sl += __shfl_xor_sync(0xffffffffu, sl, o);
        sr += __shfl_xor_sync(0xffffffffu, sr, o);
    }
    if (lane == 0) {
        d_el[p][n * N_HEADS + h] = sl;
        d_er[p][n * N_HEADS + h] = sr;
    }
}

// ------------------------------------------------ CSR build by dst (batched)
__global__ void hist_kernel(const int* __restrict__ dst) {
    int p = blockIdx.y;
    int e = blockIdx.x * blockDim.x + threadIdx.x;
    if (e < NE) atomicAdd(&d_counts[p][dst[p * NE + e]], 1);
}

__global__ void scan_kernel() {
    int p = blockIdx.x;
    __shared__ int sh[1024];
    int t = threadIdx.x;
    int base = t * 8;
    int loc[8];
    int s = 0;
#pragma unroll
    for (int i = 0; i < 8; i++) { loc[i] = s; s += d_counts[p][base + i]; }
    sh[t] = s;
    __syncthreads();
    for (int ofs = 1; ofs < 1024; ofs <<= 1) {
        int v = (t >= ofs) ? sh[t - ofs] : 0;
        __syncthreads();
        sh[t] += v;
        __syncthreads();
    }
    int pre = (t == 0) ? 0 : sh[t - 1];
#pragma unroll
    for (int i = 0; i < 8; i++) {
        int o = pre + loc[i];
        d_offsets[p][base + i] = o;
        d_cursor[p][base + i] = o;
    }
    if (t == 1023) d_offsets[p][N_NODES] = sh[1023];
}

__global__ void csr_scatter_kernel(const int* __restrict__ src,
                                   const int* __restrict__ dst) {
    int p = blockIdx.y;
    int e = blockIdx.x * blockDim.x + threadIdx.x;
    if (e < NE) {
        int pos = atomicAdd(&d_cursor[p][dst[p * NE + e]], 1);
        d_csrsrc[p][pos] = src[p * NE + e];
    }
}

// ------------------------------------------------ aggregation for one p
__global__ void gat_aggregate_kernel(const float* __restrict__ bias, int p) {
    int dn = blockIdx.x;
    int h = threadIdx.x >> 5;
    int lane = threadIdx.x & 31;
    int s0 = d_offsets[p][dn], s1 = d_offsets[p][dn + 1];
    float erv = d_er[p][dn * N_HEADS + h];
    const float* __restrict__ el = d_el[p];
    const int* __restrict__ csrc = d_csrsrc[p];
    const __half* fb = &d_feat16[p][h * HIDD + lane * 2];

    float ssum = 0.f, accx = 0.f, accy = 0.f;
    int i = s0;
    for (; i + 8 <= s1; i += 8) {
        int sx[8];
#pragma unroll
        for (int u = 0; u < 8; u++) sx[u] = csrc[i + u];
        float ex[8];
#pragma unroll
        for (int u = 0; u < 8; u++) ex[u] = el[sx[u] * N_HEADS + h];
        float2 fx[8];
#pragma unroll
        for (int u = 0; u < 8; u++)
            fx[u] = __half22float2(*(const __half2*)(fb + (size_t)sx[u] * HD));
#pragma unroll
        for (int u = 0; u < 8; u++) {
            float v = ex[u] + erv;
            v = v > 0.f ? v : 0.2f * v;
            float a = __expf(v);
            ssum += a;
            accx += a * fx[u].x;
            accy += a * fx[u].y;
        }
    }
    for (; i < s1; i++) {
        int s = csrc[i];
        float ev = el[s * N_HEADS + h] + erv;
        ev = ev > 0.f ? ev : 0.2f * ev;
        float a = __expf(ev);
        float2 f = __half22float2(*(const __half2*)(fb + (size_t)s * HD));
        ssum += a;
        accx += a * f.x;
        accy += a * f.y;
    }
    float inv = ssum > 0.f ? 1.f / ssum : 0.f;
    if (lane == 0) d_invd[p][dn * N_HEADS + h] = inv;

    float bx = bias[p * HD + h * HIDD + lane * 2];
    float by = bias[p * HD + h * HIDD + lane * 2 + 1];
    float ox = accx * inv + bx, oy = accy * inv + by;
    ox = ox > 0.f ? ox : (__expf(ox) - 1.f);
    oy = oy > 0.f ? oy : (__expf(oy) - 1.f);
    *(__half2*)&d_zp16[p][(size_t)dn * HD + h * HIDD + lane * 2] =
        __floats2half2_rn(ox, oy);
}

// ------------------------------------------------ semantic attention
__global__ void sem_v_kernel(const float* __restrict__ w1,
                             const float* __restrict__ w2,
                             const float* __restrict__ b1) {
    int k = threadIdx.x + blockIdx.x * blockDim.x;
    float s = 0.f;
    for (int j = 0; j < 128; j++) s += w1[k * 128 + j] * w2[j];
    d_v[k] = s;
    if (k == 0) {
        float c = 0.f;
        for (int j = 0; j < 128; j++) c += b1[j] * w2[j];
        d_c = c;
    }
}

// per-p incremental wsum (launched right after aggregate(p))
__global__ void sem_w_p_kernel(int p) {
    int n = (blockIdx.x * blockDim.x + threadIdx.x) >> 5;
    int lane = threadIdx.x & 31;
    if (n >= N_NODES) return;
    const __half* z = &d_zp16[p][(size_t)n * HD];
    float s = 0.f;
#pragma unroll
    for (int k2 = lane; k2 < HD / 2; k2 += 32) {
        float2 f = __half22float2(((const __half2*)z)[k2]);
        s += f.x * d_v[k2 * 2] + f.y * d_v[k2 * 2 + 1];
    }
#pragma unroll
    for (int o = 16; o; o >>= 1) s += __shfl_xor_sync(0xffffffffu, s, o);
    if (lane == 0) {
        float w = s + d_c;
        w = w > 0.f ? w : 0.01f * w;
        atomicAdd(&d_wsum[p], w);
    }
}

// ------------------------------------------------ out = (Σp beta_p zp) @ pred_w + pred_b
__global__ void out_kernel(const float* __restrict__ pw,
                           const float* __restrict__ pb,
                           float* __restrict__ out) {
    __shared__ float zs[HD];
    int n = blockIdx.x;
    int t = threadIdx.x;   // 64
    float3 bt = compute_beta();
    for (int k2 = t; k2 < HD / 2; k2 += 64) {
        size_t off2 = (size_t)n * (HD / 2) + k2;
        float2 a = __half22float2(((const __half2*)d_zp16[0])[off2]);
        float2 b = __half22float2(((const __half2*)d_zp16[1])[off2]);
        float2 c = __half22float2(((const __half2*)d_zp16[2])[off2]);
        zs[k2 * 2]     = bt.x * a.x + bt.y * b.x + bt.z * c.x;
        zs[k2 * 2 + 1] = bt.x * a.y + bt.y * b.y + bt.z * c.y;
    }
    __syncthreads();
    float acc = pb[t];
#pragma unroll 8
    for (int k = 0; k < HD; k++) acc += zs[k] * pw[k * OUT_F + t];
    out[(size_t)n * OUT_F + t] = acc;
}

// ------------------------------------------------ atten scatter (fused alpha+beta)
__global__ void atten_scatter_kernel(const int* __restrict__ src,
                                     const int* __restrict__ dst,
                                     float* __restrict__ atten) {
    int p = blockIdx.y;
    int e = blockIdx.x * blockDim.x + threadIdx.x;
    if (e >= NE) return;
    float3 bt = compute_beta();
    float betap = (p == 0) ? bt.x : (p == 1) ? bt.y : bt.z;
    int s = src[p * NE + e];
    int d = dst[p * NE + e];
    const float* elrow = &d_el[p][s * N_HEADS];
    const float* errow = &d_er[p][d * N_HEADS];
    const float* invrow = &d_invd[p][d * N_HEADS];
    float a = 0.f;
#pragma unroll
    for (int h = 0; h < N_HEADS; h++) {
        float ev = elrow[h] + errow[h];
        ev = ev > 0.f ? ev : 0.2f * ev;
        a += __expf(ev) * invrow[h];
    }
    float v = a * 0.125f * betap;
    atomicAdd(&atten[(size_t)s * N_NODES + d], v);
}

// ---------------------------------------------------------------- launcher
extern "C" void kernel_launch(void* const* d_in, const int* in_sizes, int n_in,
                              void* d_out, int out_size) {
    const float* h    = (const float*)d_in[0];
    const int*   esrc = (const int*)d_in[1];
    const int*   edst = (const int*)d_in[2];
    const float* fc   = (const float*)d_in[3];
    const float* al   = (const float*)d_in[4];
    const float* ar   = (const float*)d_in[5];
    const float* bias = (const float*)d_in[6];
    const float* w1   = (const float*)d_in[7];
    const float* b1   = (const float*)d_in[8];
    const float* w2   = (const float*)d_in[9];
    const float* pw   = (const float*)d_in[10];
    const float* pb   = (const float*)d_in[11];

    const long long SZ_OUT   = (long long)N_NODES * OUT_F;
    const long long SZ_ATTEN = (long long)N_NODES * N_NODES;
    long long osz = (long long)out_size;

    float* out_ptr = nullptr;
    float* atten_ptr = nullptr;
    if (osz >= SZ_OUT + SZ_ATTEN) {
        out_ptr = (float*)d_out;
        atten_ptr = out_ptr + SZ_OUT;
    } else if (osz == SZ_OUT) {
        out_ptr = (float*)d_out;
    } else if (osz == SZ_ATTEN) {
        atten_ptr = (float*)d_out;
    } else {
        out_ptr = (float*)d_out;
    }

    // streams: A = CSR, B = zero_atten + scatter, C = eler/aggregate/sem chain
    static cudaStream_t sA = 0, sB = 0, sC = 0;
    static cudaEvent_t evFork = nullptr, evCSR = nullptr, evW = nullptr,
                       evB = nullptr, evC = nullptr;
    static cudaEvent_t evG[P_META] = {nullptr, nullptr, nullptr};
    static int streams_ok = -1;
    if (streams_ok < 0) {
        cudaStream_t t1, t2, t3;
        cudaEvent_t e0, e1, e2, e3, e4, g0, g1, g2;
        bool ok =
            cudaStreamCreateWithFlags(&t1, cudaStreamNonBlocking) == cudaSuccess &&
            cudaStreamCreateWithFlags(&t2, cudaStreamNonBlocking) == cudaSuccess &&
            cudaStreamCreateWithFlags(&t3, cudaStreamNonBlocking) == cudaSuccess &&
            cudaEventCreateWithFlags(&e0, cudaEventDisableTiming) == cudaSuccess &&
            cudaEventCreateWithFlags(&e1, cudaEventDisableTiming) == cudaSuccess &&
            cudaEventCreateWithFlags(&e2, cudaEventDisableTiming) == cudaSuccess &&
            cudaEventCreateWithFlags(&e3, cudaEventDisableTiming) == cudaSuccess &&
            cudaEventCreateWithFlags(&e4, cudaEventDisableTiming) == cudaSuccess &&
            cudaEventCreateWithFlags(&g0, cudaEventDisableTiming) == cudaSuccess &&
            cudaEventCreateWithFlags(&g1, cudaEventDisableTiming) == cudaSuccess &&
            cudaEventCreateWithFlags(&g2, cudaEventDisableTiming) == cudaSuccess;
        if (ok) {
            sA = t1; sB = t2; sC = t3;
            evFork = e0; evCSR = e1; evW = e2; evB = e3; evC = e4;
            evG[0] = g0; evG[1] = g1; evG[2] = g2;
            streams_ok = 1;
        } else {
            streams_ok = 0;
        }
    }

    if (!streams_ok) {
        // sequential fallback
        zero_misc_kernel<<<dim3(N_NODES / 256, P_META), 256>>>();
        if (atten_ptr)
            zero_atten_kernel<<<(N_NODES * (N_NODES / 4)) / 256, 256>>>(
                (float4*)atten_ptr);
        hist_kernel<<<dim3(NE / 256, P_META), 256>>>(edst);
        scan_kernel<<<P_META, 1024>>>();
        csr_scatter_kernel<<<dim3(NE / 256, P_META), 256>>>(esrc, edst);
        sem_v_kernel<<<2, 256>>>(w1, w2, b1);
        for (int p = 0; p < P_META; p++) {
            gemm_feat_kernel<<<dim3(HD / 128, N_NODES / 128), 256>>>(h, fc, p);
            eler_kernel<<<N_NODES, 256>>>(al, ar, p);
            gat_aggregate_kernel<<<N_NODES, 256>>>(bias, p);
            sem_w_p_kernel<<<(N_NODES * 32) / 256, 256>>>(p);
        }
        if (out_ptr) out_kernel<<<N_NODES, 64>>>(pw, pb, out_ptr);
        if (atten_ptr)
            atten_scatter_kernel<<<dim3(NE / 256, P_META), 256>>>(esrc, edst,
                                                                  atten_ptr);
        return;
    }

    cudaEventRecord(evFork, (cudaStream_t)0);
    cudaStreamWaitEvent(sA, evFork, 0);
    cudaStreamWaitEvent(sB, evFork, 0);
    cudaStreamWaitEvent(sC, evFork, 0);

    // stream A: CSR build chain
    zero_misc_kernel<<<dim3(N_NODES / 256, P_META), 256, 0, sA>>>();
    hist_kernel<<<dim3(NE / 256, P_META), 256, 0, sA>>>(edst);
    scan_kernel<<<P_META, 1024, 0, sA>>>();
    csr_scatter_kernel<<<dim3(NE / 256, P_META), 256, 0, sA>>>(esrc, edst);
    cudaEventRecord(evCSR, sA);

    // stream B: atten zero-fill + sem_v (independent prep)
    if (atten_ptr)
        zero_atten_kernel<<<(N_NODES * (N_NODES / 4)) / 256, 256, 0, sB>>>(
            (float4*)atten_ptr);
    sem_v_kernel<<<2, 256, 0, sB>>>(w1, w2, b1);

    // main: back-to-back GEMMs only
    for (int p = 0; p < P_META; p++) {
        gemm_feat_kernel<<<dim3(HD / 128, N_NODES / 128), 256>>>(h, fc, p);
        cudaEventRecord(evG[p], (cudaStream_t)0);
    }

    // stream C: eler(p) -> aggregate(p) -> sem_w(p), pipelined vs gemm(p+1)
    cudaStreamWaitEvent(sC, evCSR, 0);
    for (int p = 0; p < P_META; p++) {
        cudaStreamWaitEvent(sC, evG[p], 0);
        eler_kernel<<<N_NODES, 256, 0, sC>>>(al, ar, p);
        gat_aggregate_kernel<<<N_NODES, 256, 0, sC>>>(bias, p);
        sem_w_p_kernel<<<(N_NODES * 32) / 256, 256, 0, sC>>>(p);
    }
    cudaEventRecord(evW, sC);

    // atten_scatter on stream B immediately after wsum; out on stream C
    if (atten_ptr) {
        cudaStreamWaitEvent(sB, evW, 0);
        atten_scatter_kernel<<<dim3(NE / 256, P_META), 256, 0, sB>>>(
            esrc, edst, atten_ptr);
    }
    cudaEventRecord(evB, sB);

    if (out_ptr)
        out_kernel<<<N_NODES, 64, 0, sC>>>(pw, pb, out_ptr);
    cudaEventRecord(evC, sC);

    // join everything back to main
    cudaStreamWaitEvent((cudaStream_t)0, evC, 0);
    cudaStreamWaitEvent((cudaStream_t)0, evB, 0);
}